// round 1
// baseline (speedup 1.0000x reference)
#include <cuda_runtime.h>
#include <math.h>

// Problem constants
#define BB   256   // batch
#define NH   850   // nhid = ninp
#define TT   70    // timesteps

// GEMM tile config
#define BM 64
#define BN 64      // N measured in column-PAIRS (col j and j+850 computed together)
#define BK 16

// Scratch: 9 DAG states, each [B, NH] fp32  (~7.8 MB static)
__device__ float g_states[9][BB * NH];

// Edge table: {pred_state, out_state, weight_idx, act}
// act: 0=tanh 1=relu 2=sigmoid 3=identity
struct Edge { int pred, out, w, act; };
__constant__ Edge c_edges[8] = {
    {0, 1, 0, 0},  // edge0: tanh, pred s0
    {1, 2, 1, 1},  // edge1: relu, pred s1
    {1, 3, 2, 1},  // edge2: relu, pred s1
    {1, 4, 3, 3},  // edge3: identity, pred s1
    {2, 5, 4, 0},  // edge4: tanh, pred s2
    {5, 6, 5, 2},  // edge5: sigmoid, pred s5
    {3, 7, 6, 0},  // edge6: tanh, pred s3
    {5, 8, 7, 1},  // edge7: relu, pred s5
};

__device__ __forceinline__ float actf(float x, int a) {
    switch (a) {
        case 0:  return tanhf(x);
        case 1:  return fmaxf(x, 0.f);
        case 2:  return 1.f / (1.f + __expf(-x));
        default: return x;
    }
}
__device__ __forceinline__ float sigf(float x) { return 1.f / (1.f + __expf(-x)); }

// Core fused GEMM + highway epilogue.
// Computes, for a [BM x BN]-pair tile:
//   C[b, j]       = sum_k A[b, k] * W[k, j]         (j in [0, NH))
//   H[b, j]       = sum_k A[b, k] * W[k, j + NH]
//   sOut[b, j]    = sPrev[b,j] + sigmoid(C)*(act(H) - sPrev[b,j])
// SPLIT: A is concat(A0[B,NH], A1[B,NH]) along K (K = 2*NH); else A = A0, K = NH.
template <bool SPLIT>
__device__ __forceinline__ void gemm_core(
    const float* __restrict__ A0, const float* __restrict__ A1, int K,
    const float* __restrict__ W, const float* __restrict__ sPrev,
    float* __restrict__ sOut, int act)
{
    __shared__ float As[BK][BM];
    __shared__ float Wc[BK][BN];
    __shared__ float Wh[BK][BN];

    const int tid = threadIdx.x;        // 256 threads
    const int tx  = tid & 15;           // N direction (16)
    const int ty  = tid >> 4;           // M direction (16)
    const int n0  = blockIdx.x * BN;
    const int m0  = blockIdx.y * BM;

    float accC[4][4] = {};
    float accH[4][4] = {};

    for (int k0 = 0; k0 < K; k0 += BK) {
        // ---- load A tile: BM x BK = 1024 floats, 4 per thread ----
        #pragma unroll
        for (int i = 0; i < 4; i++) {
            int idx = tid + i * 256;
            int m = idx >> 4;           // 0..63
            int k = idx & 15;           // 0..15
            int gk = k0 + k;
            int row = m0 + m;           // always < 256
            float v = 0.f;
            if (gk < K) {
                if (SPLIT)
                    v = (gk < NH) ? A0[row * NH + gk] : A1[row * NH + (gk - NH)];
                else
                    v = A0[row * NH + gk];
            }
            As[k][m] = v;
        }
        // ---- load W tiles (c-half and h-half): each BK x BN = 1024 floats ----
        #pragma unroll
        for (int i = 0; i < 4; i++) {
            int idx = tid + i * 256;
            int k = idx >> 6;           // 0..15
            int n = idx & 63;           // 0..63
            int gk = k0 + k;
            int gn = n0 + n;
            float vc = 0.f, vh = 0.f;
            if (gk < K && gn < NH) {
                const float* wrow = W + (size_t)gk * (2 * NH);
                vc = wrow[gn];
                vh = wrow[gn + NH];
            }
            Wc[k][n] = vc;
            Wh[k][n] = vh;
        }
        __syncthreads();

        #pragma unroll
        for (int kk = 0; kk < BK; kk++) {
            float4 a4  = *reinterpret_cast<const float4*>(&As[kk][ty * 4]);
            float4 c4  = *reinterpret_cast<const float4*>(&Wc[kk][tx * 4]);
            float4 h4  = *reinterpret_cast<const float4*>(&Wh[kk][tx * 4]);
            float a[4]  = {a4.x, a4.y, a4.z, a4.w};
            float wc[4] = {c4.x, c4.y, c4.z, c4.w};
            float wh[4] = {h4.x, h4.y, h4.z, h4.w};
            #pragma unroll
            for (int i = 0; i < 4; i++)
                #pragma unroll
                for (int j = 0; j < 4; j++) {
                    accC[i][j] += a[i] * wc[j];
                    accH[i][j] += a[i] * wh[j];
                }
        }
        __syncthreads();
    }

    // ---- fused highway epilogue ----
    #pragma unroll
    for (int i = 0; i < 4; i++) {
        int row = m0 + ty * 4 + i;
        #pragma unroll
        for (int j = 0; j < 4; j++) {
            int col = n0 + tx * 4 + j;
            if (col < NH) {
                float sp = sPrev[row * NH + col];
                float g  = sigf(accC[i][j]);
                sOut[row * NH + col] = sp + g * (actf(accH[i][j], act) - sp);
            }
        }
    }
}

// Step init: s0 = h + sigmoid(c0) * (tanh(h0) - h), [x, h] @ W0, K = 1700
__global__ __launch_bounds__(256)
void gemm0_kernel(const float* __restrict__ x, const float* __restrict__ h,
                  const float* __restrict__ W0)
{
    gemm_core<true>(x, h, 2 * NH, W0, h, g_states[0], /*tanh*/ 0);
}

// Edge GEMMs; blockIdx.z selects which edge of this dependency level
__global__ __launch_bounds__(256)
void edge_kernel(const float* __restrict__ Ws, int e0, int e1, int e2)
{
    int eidx = (blockIdx.z == 0) ? e0 : ((blockIdx.z == 1) ? e1 : e2);
    Edge e = c_edges[eidx];
    const float* W = Ws + (size_t)e.w * NH * (2 * NH);
    gemm_core<false>(g_states[e.pred], nullptr, NH, W,
                     g_states[e.pred], g_states[e.out], e.act);
}

// h_new = mean(s1..s8), written straight into the output tensor at step t
__global__ void mean_kernel(float* __restrict__ out)
{
    int i = blockIdx.x * blockDim.x + threadIdx.x;
    if (i < BB * NH) {
        float s = 0.f;
        #pragma unroll
        for (int j = 1; j < 9; j++) s += g_states[j][i];
        out[i] = s * 0.125f;
    }
}

extern "C" void kernel_launch(void* const* d_in, const int* in_sizes, int n_in,
                              void* d_out, int out_size)
{
    const float* inputs = (const float*)d_in[0];  // [T, B, NH]
    const float* hidden = (const float*)d_in[1];  // [1, B, NH]
    const float* W0     = (const float*)d_in[2];  // [2*NH, 2*NH]
    const float* Ws     = (const float*)d_in[3];  // [8, NH, 2*NH]
    float* out = (float*)d_out;                   // [T, B, NH] + [1, B, NH]

    const dim3 blk(256);
    const int NBX = (NH + BN - 1) / BN;           // 14
    const int NBY = BB / BM;                      // 4

    for (int t = 0; t < TT; t++) {
        const float* x = inputs + (size_t)t * BB * NH;
        const float* h = (t == 0) ? hidden : out + (size_t)(t - 1) * BB * NH;
        float* ht = out + (size_t)t * BB * NH;

        // Level 0: init state s0  (K = 1700)
        gemm0_kernel<<<dim3(NBX, NBY, 1), blk>>>(x, h, W0);
        // Level 1: edge0 -> s1
        edge_kernel<<<dim3(NBX, NBY, 1), blk>>>(Ws, 0, 0, 0);
        // Level 2: edges 1,2,3 -> s2,s3,s4
        edge_kernel<<<dim3(NBX, NBY, 3), blk>>>(Ws, 1, 2, 3);
        // Level 3: edges 4,6 -> s5,s7
        edge_kernel<<<dim3(NBX, NBY, 2), blk>>>(Ws, 4, 6, 0);
        // Level 4: edges 5,7 -> s6,s8
        edge_kernel<<<dim3(NBX, NBY, 2), blk>>>(Ws, 5, 7, 0);
        // h_{t} = mean(s1..s8)
        mean_kernel<<<(BB * NH + 255) / 256, 256>>>(ht);
    }

    // Second output: final hidden = hiddens[-1]
    cudaMemcpyAsync(out + (size_t)TT * BB * NH,
                    out + (size_t)(TT - 1) * BB * NH,
                    (size_t)BB * NH * sizeof(float),
                    cudaMemcpyDeviceToDevice);
}

// round 2
// speedup vs baseline: 1.0004x; 1.0004x over previous
#include <cuda_runtime.h>
#include <math.h>

// Problem constants
#define BB   256   // batch
#define NH   850   // nhid = ninp
#define TT   70    // timesteps

// GEMM tile config
#define BM 64
#define BN 64      // N measured in column-PAIRS (col j and j+850 computed together)
#define BK 16

// Scratch: 9 DAG states, each [B, NH] fp32  (~7.8 MB static)
__device__ float g_states[9][BB * NH];

// Edge table: {pred_state, out_state, weight_idx, act}
// act: 0=tanh 1=relu 2=sigmoid 3=identity
struct Edge { int pred, out, w, act; };
__constant__ Edge c_edges[8] = {
    {0, 1, 0, 0},  // edge0: tanh, pred s0
    {1, 2, 1, 1},  // edge1: relu, pred s1
    {1, 3, 2, 1},  // edge2: relu, pred s1
    {1, 4, 3, 3},  // edge3: identity, pred s1
    {2, 5, 4, 0},  // edge4: tanh, pred s2
    {5, 6, 5, 2},  // edge5: sigmoid, pred s5
    {3, 7, 6, 0},  // edge6: tanh, pred s3
    {5, 8, 7, 1},  // edge7: relu, pred s5
};

__device__ __forceinline__ float actf(float x, int a) {
    switch (a) {
        case 0:  return tanhf(x);
        case 1:  return fmaxf(x, 0.f);
        case 2:  return 1.f / (1.f + __expf(-x));
        default: return x;
    }
}
__device__ __forceinline__ float sigf(float x) { return 1.f / (1.f + __expf(-x)); }

// Core fused GEMM + highway epilogue.
// Computes, for a [BM x BN]-pair tile:
//   C[b, j]       = sum_k A[b, k] * W[k, j]         (j in [0, NH))
//   H[b, j]       = sum_k A[b, k] * W[k, j + NH]
//   sOut[b, j]    = sPrev[b,j] + sigmoid(C)*(act(H) - sPrev[b,j])
// SPLIT: A is concat(A0[B,NH], A1[B,NH]) along K (K = 2*NH); else A = A0, K = NH.
template <bool SPLIT>
__device__ __forceinline__ void gemm_core(
    const float* __restrict__ A0, const float* __restrict__ A1, int K,
    const float* __restrict__ W, const float* __restrict__ sPrev,
    float* __restrict__ sOut, int act)
{
    __shared__ float As[BK][BM];
    __shared__ float Wc[BK][BN];
    __shared__ float Wh[BK][BN];

    const int tid = threadIdx.x;        // 256 threads
    const int tx  = tid & 15;           // N direction (16)
    const int ty  = tid >> 4;           // M direction (16)
    const int n0  = blockIdx.x * BN;
    const int m0  = blockIdx.y * BM;

    float accC[4][4] = {};
    float accH[4][4] = {};

    for (int k0 = 0; k0 < K; k0 += BK) {
        // ---- load A tile: BM x BK = 1024 floats, 4 per thread ----
        #pragma unroll
        for (int i = 0; i < 4; i++) {
            int idx = tid + i * 256;
            int m = idx >> 4;           // 0..63
            int k = idx & 15;           // 0..15
            int gk = k0 + k;
            int row = m0 + m;           // always < 256
            float v = 0.f;
            if (gk < K) {
                if (SPLIT)
                    v = (gk < NH) ? A0[row * NH + gk] : A1[row * NH + (gk - NH)];
                else
                    v = A0[row * NH + gk];
            }
            As[k][m] = v;
        }
        // ---- load W tiles (c-half and h-half): each BK x BN = 1024 floats ----
        #pragma unroll
        for (int i = 0; i < 4; i++) {
            int idx = tid + i * 256;
            int k = idx >> 6;           // 0..15
            int n = idx & 63;           // 0..63
            int gk = k0 + k;
            int gn = n0 + n;
            float vc = 0.f, vh = 0.f;
            if (gk < K && gn < NH) {
                const float* wrow = W + (size_t)gk * (2 * NH);
                vc = wrow[gn];
                vh = wrow[gn + NH];
            }
            Wc[k][n] = vc;
            Wh[k][n] = vh;
        }
        __syncthreads();

        #pragma unroll
        for (int kk = 0; kk < BK; kk++) {
            float4 a4  = *reinterpret_cast<const float4*>(&As[kk][ty * 4]);
            float4 c4  = *reinterpret_cast<const float4*>(&Wc[kk][tx * 4]);
            float4 h4  = *reinterpret_cast<const float4*>(&Wh[kk][tx * 4]);
            float a[4]  = {a4.x, a4.y, a4.z, a4.w};
            float wc[4] = {c4.x, c4.y, c4.z, c4.w};
            float wh[4] = {h4.x, h4.y, h4.z, h4.w};
            #pragma unroll
            for (int i = 0; i < 4; i++)
                #pragma unroll
                for (int j = 0; j < 4; j++) {
                    accC[i][j] += a[i] * wc[j];
                    accH[i][j] += a[i] * wh[j];
                }
        }
        __syncthreads();
    }

    // ---- fused highway epilogue ----
    #pragma unroll
    for (int i = 0; i < 4; i++) {
        int row = m0 + ty * 4 + i;
        #pragma unroll
        for (int j = 0; j < 4; j++) {
            int col = n0 + tx * 4 + j;
            if (col < NH) {
                float sp = sPrev[row * NH + col];
                float g  = sigf(accC[i][j]);
                sOut[row * NH + col] = sp + g * (actf(accH[i][j], act) - sp);
            }
        }
    }
}

// Step init: s0 = h + sigmoid(c0) * (tanh(h0) - h), [x, h] @ W0, K = 1700
__global__ __launch_bounds__(256)
void gemm0_kernel(const float* __restrict__ x, const float* __restrict__ h,
                  const float* __restrict__ W0)
{
    gemm_core<true>(x, h, 2 * NH, W0, h, g_states[0], /*tanh*/ 0);
}

// Edge GEMMs; blockIdx.z selects which edge of this dependency level
__global__ __launch_bounds__(256)
void edge_kernel(const float* __restrict__ Ws, int e0, int e1, int e2)
{
    int eidx = (blockIdx.z == 0) ? e0 : ((blockIdx.z == 1) ? e1 : e2);
    Edge e = c_edges[eidx];
    const float* W = Ws + (size_t)e.w * NH * (2 * NH);
    gemm_core<false>(g_states[e.pred], nullptr, NH, W,
                     g_states[e.pred], g_states[e.out], e.act);
}

// h_new = mean(s1..s8), written straight into the output tensor at step t
__global__ void mean_kernel(float* __restrict__ out)
{
    int i = blockIdx.x * blockDim.x + threadIdx.x;
    if (i < BB * NH) {
        float s = 0.f;
        #pragma unroll
        for (int j = 1; j < 9; j++) s += g_states[j][i];
        out[i] = s * 0.125f;
    }
}

extern "C" void kernel_launch(void* const* d_in, const int* in_sizes, int n_in,
                              void* d_out, int out_size)
{
    const float* inputs = (const float*)d_in[0];  // [T, B, NH]
    const float* hidden = (const float*)d_in[1];  // [1, B, NH]
    const float* W0     = (const float*)d_in[2];  // [2*NH, 2*NH]
    const float* Ws     = (const float*)d_in[3];  // [8, NH, 2*NH]
    float* out = (float*)d_out;                   // [T, B, NH] + [1, B, NH]

    const dim3 blk(256);
    const int NBX = (NH + BN - 1) / BN;           // 14
    const int NBY = BB / BM;                      // 4

    for (int t = 0; t < TT; t++) {
        const float* x = inputs + (size_t)t * BB * NH;
        const float* h = (t == 0) ? hidden : out + (size_t)(t - 1) * BB * NH;
        float* ht = out + (size_t)t * BB * NH;

        // Level 0: init state s0  (K = 1700)
        gemm0_kernel<<<dim3(NBX, NBY, 1), blk>>>(x, h, W0);
        // Level 1: edge0 -> s1
        edge_kernel<<<dim3(NBX, NBY, 1), blk>>>(Ws, 0, 0, 0);
        // Level 2: edges 1,2,3 -> s2,s3,s4
        edge_kernel<<<dim3(NBX, NBY, 3), blk>>>(Ws, 1, 2, 3);
        // Level 3: edges 4,6 -> s5,s7
        edge_kernel<<<dim3(NBX, NBY, 2), blk>>>(Ws, 4, 6, 0);
        // Level 4: edges 5,7 -> s6,s8
        edge_kernel<<<dim3(NBX, NBY, 2), blk>>>(Ws, 5, 7, 0);
        // h_{t} = mean(s1..s8)
        mean_kernel<<<(BB * NH + 255) / 256, 256>>>(ht);
    }

    // Second output: final hidden = hiddens[-1]
    cudaMemcpyAsync(out + (size_t)TT * BB * NH,
                    out + (size_t)(TT - 1) * BB * NH,
                    (size_t)BB * NH * sizeof(float),
                    cudaMemcpyDeviceToDevice);
}

// round 4
// speedup vs baseline: 5.2629x; 5.2606x over previous
#include <cuda_runtime.h>
#include <cstdint>
#include <math.h>

// ---------------- Problem constants ----------------
#define BB   256
#define NH   850
#define TT   70
#define PK   864            // padded K for states (27*32)
#define PK0  1728           // padded K for [x, h]  (54*32)
#define WNC  1728           // prepped weight row: [0,864)=c cols, [864,1728)=h cols

// ---------------- Global scratch (static; no allocs) ----------------
__device__ __align__(16) float g_states[9][BB * PK];          // ~8 MB
__device__ __align__(16) float g_xh[BB * PK0];                // ~1.8 MB
__device__ __align__(16) float g_w0[(size_t)PK0 * WNC];       // ~11.9 MB
__device__ __align__(16) float g_we[8][(size_t)PK * WNC];     // ~47.8 MB

struct Edge { int pred, out, w, act; };
__constant__ Edge c_edges[8] = {
    {0, 1, 0, 0}, {1, 2, 1, 1}, {1, 3, 2, 1}, {1, 4, 3, 3},
    {2, 5, 4, 0}, {5, 6, 5, 2}, {3, 7, 6, 0}, {5, 8, 7, 1},
};

// ---------------- Helpers ----------------
__device__ __forceinline__ uint32_t cvt_tf32(float x) {
    uint32_t u;
    asm("cvt.rna.tf32.f32 %0, %1;" : "=r"(u) : "f"(x));
    return u;
}
__device__ __forceinline__ float tf32r(float x) { return __uint_as_float(cvt_tf32(x)); }

__device__ __forceinline__ void cp16(void* dst, const void* src) {
    uint32_t d = (uint32_t)__cvta_generic_to_shared(dst);
    asm volatile("cp.async.cg.shared.global [%0], [%1], 16;" :: "r"(d), "l"(src) : "memory");
}
__device__ __forceinline__ void cp_commit() {
    asm volatile("cp.async.commit_group;" ::: "memory");
}
template <int N> __device__ __forceinline__ void cp_wait() {
    asm volatile("cp.async.wait_group %0;" :: "n"(N) : "memory");
}

__device__ __forceinline__ void mma8(float* d, const uint32_t* a, uint32_t b0, uint32_t b1) {
    asm volatile("mma.sync.aligned.m16n8k8.row.col.f32.tf32.tf32.f32 "
        "{%0,%1,%2,%3}, {%4,%5,%6,%7}, {%8,%9}, {%0,%1,%2,%3};"
        : "+f"(d[0]), "+f"(d[1]), "+f"(d[2]), "+f"(d[3])
        : "r"(a[0]), "r"(a[1]), "r"(a[2]), "r"(a[3]), "r"(b0), "r"(b1));
}

__device__ __forceinline__ float actf(float x, int a) {
    if (a == 0) return tanhf(x);
    if (a == 1) return fmaxf(x, 0.f);
    if (a == 2) return 1.f / (1.f + __expf(-x));
    return x;
}

// ---------------- GEMM core ----------------
// CTA tile: M=64 rows x 32 col-pairs (64 output cols incl. c/h halves).
// 128 threads = 4 warps in 2(M) x 2(N); warp tile 32 x 16 pairs.
// A: [256 x Kpad] fp32 (padding zeros).  W: prepped [Kpad x 1728] tf32-rounded,
// cols [0,864) = c-half, [864,1728) = h-half.
// Out[r][c] = P[r][c] + sigmoid(C) * (act(H) - P[r][c]).
__device__ __forceinline__ void load_stage(
    float (*As)[64][36], float (*Bs)[32][72], int s, int kt,
    const float* __restrict__ A, int strideA, const float* __restrict__ W,
    int m0, int j0, int tid)
{
    const int k0 = kt * 32;
    #pragma unroll
    for (int i = 0; i < 4; i++) {
        int idx = tid + i * 128;
        int r = idx >> 3, c = idx & 7;
        cp16(&As[s][r][c * 4], A + (size_t)(m0 + r) * strideA + k0 + c * 4);
    }
    #pragma unroll
    for (int i = 0; i < 4; i++) {
        int idx = tid + i * 128;
        int kk = idx >> 4, c = idx & 15;
        const float* src = W + (size_t)(k0 + kk) * WNC
                             + (c < 8 ? (j0 + c * 4) : (864 + j0 + (c - 8) * 4));
        cp16(&Bs[s][kk][c * 4], src);
    }
}

__device__ __forceinline__ void gemm_core(
    const float* __restrict__ A, int strideA, const float* __restrict__ W,
    const float* __restrict__ P, int strideP, float* __restrict__ Out,
    int act, int niter)
{
    __shared__ float As[2][64][36];   // stride 36: conflict-free A-frag LDS
    __shared__ float Bs[2][32][72];   // stride 72: conflict-free B-frag LDS

    const int tid = threadIdx.x, wid = tid >> 5, lid = tid & 31;
    const int wm = wid & 1, wn = wid >> 1;          // 2 x 2 warp grid
    const int j0 = blockIdx.x * 32;                 // col-pair tile
    const int m0 = blockIdx.y * 64;                 // row tile
    const int lr = lid >> 2, lc = lid & 3;

    float cacc[2][2][4], hacc[2][2][4];
    #pragma unroll
    for (int a = 0; a < 2; a++)
        #pragma unroll
        for (int b = 0; b < 2; b++)
            #pragma unroll
            for (int c = 0; c < 4; c++) { cacc[a][b][c] = 0.f; hacc[a][b][c] = 0.f; }

    load_stage(As, Bs, 0, 0, A, strideA, W, m0, j0, tid);
    cp_commit();

    for (int it = 0; it < niter; it++) {
        const int buf = it & 1;
        if (it + 1 < niter) {
            load_stage(As, Bs, buf ^ 1, it + 1, A, strideA, W, m0, j0, tid);
            cp_commit();
            cp_wait<1>();
        } else {
            cp_wait<0>();
        }
        __syncthreads();

        #pragma unroll
        for (int ks = 0; ks < 4; ks++) {
            uint32_t af[2][4];
            const int k = ks * 8 + lc;
            #pragma unroll
            for (int mf = 0; mf < 2; mf++) {
                int r = wm * 32 + mf * 16 + lr;
                af[mf][0] = cvt_tf32(As[buf][r][k]);
                af[mf][1] = cvt_tf32(As[buf][r + 8][k]);
                af[mf][2] = cvt_tf32(As[buf][r][k + 4]);
                af[mf][3] = cvt_tf32(As[buf][r + 8][k + 4]);
            }
            #pragma unroll
            for (int nf = 0; nf < 2; nf++) {
                int col = wn * 16 + nf * 8 + lr;
                uint32_t bc0 = __float_as_uint(Bs[buf][k][col]);
                uint32_t bc1 = __float_as_uint(Bs[buf][k + 4][col]);
                uint32_t bh0 = __float_as_uint(Bs[buf][k][col + 32]);
                uint32_t bh1 = __float_as_uint(Bs[buf][k + 4][col + 32]);
                #pragma unroll
                for (int mf = 0; mf < 2; mf++) {
                    mma8(cacc[mf][nf], af[mf], bc0, bc1);
                    mma8(hacc[mf][nf], af[mf], bh0, bh1);
                }
            }
        }
        __syncthreads();
    }

    // fused highway epilogue
    #pragma unroll
    for (int mf = 0; mf < 2; mf++) {
        #pragma unroll
        for (int nf = 0; nf < 2; nf++) {
            const int r0 = m0 + wm * 32 + mf * 16 + lr;
            const int c0 = j0 + wn * 16 + nf * 8 + lc * 2;
            #pragma unroll
            for (int e = 0; e < 4; e++) {
                int r = r0 + (e >> 1) * 8;
                int c = c0 + (e & 1);
                if (c < NH) {
                    float sp = P[(size_t)r * strideP + c];
                    float g  = 1.f / (1.f + __expf(-cacc[mf][nf][e]));
                    float av = actf(hacc[mf][nf][e], act);
                    Out[(size_t)r * PK + c] = sp + g * (av - sp);
                }
            }
        }
    }
}

__global__ __launch_bounds__(128) void gemm0_kernel() {
    gemm_core(g_xh, PK0, g_w0, g_xh + PK, PK0, g_states[0], 0, PK0 / 32);
}
__global__ __launch_bounds__(128) void edge_kernel(int e0, int e1, int e2) {
    int e = (blockIdx.z == 0) ? e0 : ((blockIdx.z == 1) ? e1 : e2);
    Edge E = c_edges[e];
    gemm_core(g_states[E.pred], PK, g_we[E.w],
              g_states[E.pred], PK, g_states[E.out], E.act, PK / 32);
}

// ---------------- Weight prep (padded, c/h-paired, tf32-rounded) ----------------
__global__ void prep_w0(const float* __restrict__ W0) {
    size_t i = (size_t)blockIdx.x * blockDim.x + threadIdx.x;
    if (i >= (size_t)PK0 * WNC) return;
    int k = (int)(i / WNC), n = (int)(i % WNC);
    int kr = (k < NH) ? k : ((k >= PK && k < PK + NH) ? (NH + k - PK) : -1);
    int nc = (n < 864) ? ((n < NH) ? n : -1)
                       : ((n - 864 < NH) ? (NH + n - 864) : -1);
    float v = 0.f;
    if (kr >= 0 && nc >= 0) v = W0[(size_t)kr * (2 * NH) + nc];
    g_w0[i] = tf32r(v);
}
__global__ void prep_we(const float* __restrict__ Ws) {
    size_t i = (size_t)blockIdx.x * blockDim.x + threadIdx.x;
    if (i >= (size_t)8 * PK * WNC) return;
    int e = (int)(i / ((size_t)PK * WNC));
    size_t r = i % ((size_t)PK * WNC);
    int k = (int)(r / WNC), n = (int)(r % WNC);
    int nc = (n < 864) ? ((n < NH) ? n : -1)
                       : ((n - 864 < NH) ? (NH + n - 864) : -1);
    float v = 0.f;
    if (k < NH && nc >= 0) v = Ws[((size_t)e * NH + k) * (2 * NH) + nc];
    g_we[e][(size_t)k * WNC + n] = tf32r(v);
}

// ---------------- Setup / epilogue kernels ----------------
__global__ void zero_kernel() {
    int i = blockIdx.x * blockDim.x + threadIdx.x;
    if (i < 9 * BB * PK) (&g_states[0][0])[i] = 0.f;
    if (i < BB * PK0)    g_xh[i] = 0.f;
}
__global__ void stage0_kernel(const float* __restrict__ x0, const float* __restrict__ h0) {
    int i = blockIdx.x * blockDim.x + threadIdx.x;
    if (i < BB * NH) {
        int b = i / NH, j = i % NH;
        g_xh[b * PK0 + j]      = x0[i];
        g_xh[b * PK0 + PK + j] = h0[i];
    }
}
__global__ void mean_kernel(const float* __restrict__ inputs, float* __restrict__ out, int t) {
    int i = blockIdx.x * blockDim.x + threadIdx.x;
    if (i < BB * NH) {
        int b = i / NH, j = i % NH;
        float s = 0.f;
        #pragma unroll
        for (int st = 1; st < 9; st++) s += g_states[st][b * PK + j];
        s *= 0.125f;
        out[(size_t)t * (BB * NH) + i] = s;
        g_xh[b * PK0 + PK + j] = s;
        if (t + 1 < TT) g_xh[b * PK0 + j] = inputs[(size_t)(t + 1) * (BB * NH) + i];
    }
}

// ---------------- Host ----------------
extern "C" void kernel_launch(void* const* d_in, const int* in_sizes, int n_in,
                              void* d_out, int out_size)
{
    const float* inputs = (const float*)d_in[0];  // [T, B, NH]
    const float* hidden = (const float*)d_in[1];  // [1, B, NH]
    const float* W0     = (const float*)d_in[2];  // [2*NH, 2*NH]
    const float* Ws     = (const float*)d_in[3];  // [8, NH, 2*NH]
    float* out = (float*)d_out;

    zero_kernel<<<(9 * BB * PK + 255) / 256, 256>>>();
    prep_w0<<<(int)(((size_t)PK0 * WNC + 255) / 256), 256>>>(W0);
    prep_we<<<(int)(((size_t)8 * PK * WNC + 255) / 256), 256>>>(Ws);
    stage0_kernel<<<(BB * NH + 255) / 256, 256>>>(inputs, hidden);

    const dim3 blk(128);
    for (int t = 0; t < TT; t++) {
        gemm0_kernel<<<dim3(27, 4, 1), blk>>>();
        edge_kernel<<<dim3(27, 4, 1), blk>>>(0, 0, 0);
        edge_kernel<<<dim3(27, 4, 3), blk>>>(1, 2, 3);
        edge_kernel<<<dim3(27, 4, 2), blk>>>(4, 6, 0);
        edge_kernel<<<dim3(27, 4, 2), blk>>>(5, 7, 0);
        mean_kernel<<<(BB * NH + 255) / 256, 256>>>(inputs, out, t);
    }
    cudaMemcpyAsync(out + (size_t)TT * BB * NH, out + (size_t)(TT - 1) * BB * NH,
                    (size_t)BB * NH * sizeof(float), cudaMemcpyDeviceToDevice);
}